// round 1
// baseline (speedup 1.0000x reference)
#include <cuda_runtime.h>

#define N_ROWS 8192
#define D_DIM  1024
#define THREADS 256   // 1024 floats / 4 (float4) = 256 loads per matrix per row

__device__ float g_sqerr[N_ROWS];

__global__ __launch_bounds__(THREADS)
void cosine_row_kernel(const float* __restrict__ A,
                       const float* __restrict__ B,
                       const float* __restrict__ labels) {
    const int row = blockIdx.x;
    const int t   = threadIdx.x;

    const float4* a4 = reinterpret_cast<const float4*>(A + (size_t)row * D_DIM);
    const float4* b4 = reinterpret_cast<const float4*>(B + (size_t)row * D_DIM);

    const float4 av = a4[t];
    const float4 bv = b4[t];

    float dot = av.x * bv.x + av.y * bv.y + av.z * bv.z + av.w * bv.w;
    float na  = av.x * av.x + av.y * av.y + av.z * av.z + av.w * av.w;
    float nb  = bv.x * bv.x + bv.y * bv.y + bv.z * bv.z + bv.w * bv.w;

    // Warp reduction (3 values)
    #pragma unroll
    for (int off = 16; off > 0; off >>= 1) {
        dot += __shfl_down_sync(0xFFFFFFFFu, dot, off);
        na  += __shfl_down_sync(0xFFFFFFFFu, na,  off);
        nb  += __shfl_down_sync(0xFFFFFFFFu, nb,  off);
    }

    // Cross-warp reduction: 8 warps
    __shared__ float s_dot[8], s_na[8], s_nb[8];
    const int wid = t >> 5;
    const int lid = t & 31;
    if (lid == 0) { s_dot[wid] = dot; s_na[wid] = na; s_nb[wid] = nb; }
    __syncthreads();

    if (wid == 0) {
        dot = (lid < 8) ? s_dot[lid] : 0.0f;
        na  = (lid < 8) ? s_na[lid]  : 0.0f;
        nb  = (lid < 8) ? s_nb[lid]  : 0.0f;
        #pragma unroll
        for (int off = 4; off > 0; off >>= 1) {
            dot += __shfl_down_sync(0xFFFFFFFFu, dot, off);
            na  += __shfl_down_sync(0xFFFFFFFFu, na,  off);
            nb  += __shfl_down_sync(0xFFFFFFFFu, nb,  off);
        }
        if (lid == 0) {
            const float score = dot * rsqrtf(na * nb);
            const float diff  = score - labels[row];
            g_sqerr[row] = diff * diff;
        }
    }
}

__global__ __launch_bounds__(1024)
void mse_reduce_kernel(float* __restrict__ out) {
    const int t = threadIdx.x;
    float sum = 0.0f;
    #pragma unroll
    for (int i = 0; i < N_ROWS / 1024; i++)
        sum += g_sqerr[t + i * 1024];

    #pragma unroll
    for (int off = 16; off > 0; off >>= 1)
        sum += __shfl_down_sync(0xFFFFFFFFu, sum, off);

    __shared__ float s_sum[32];
    const int wid = t >> 5;
    const int lid = t & 31;
    if (lid == 0) s_sum[wid] = sum;
    __syncthreads();

    if (wid == 0) {
        sum = (lid < 32) ? s_sum[lid] : 0.0f;
        #pragma unroll
        for (int off = 16; off > 0; off >>= 1)
            sum += __shfl_down_sync(0xFFFFFFFFu, sum, off);
        if (lid == 0)
            out[0] = sum * (1.0f / (float)N_ROWS);
    }
}

extern "C" void kernel_launch(void* const* d_in, const int* in_sizes, int n_in,
                              void* d_out, int out_size) {
    const float* A      = (const float*)d_in[0];  // issues_1_geb [8192,1024]
    const float* B      = (const float*)d_in[1];  // issues_2_geb [8192,1024]
    const float* labels = (const float*)d_in[2];  // labels [8192]
    float* out = (float*)d_out;

    cosine_row_kernel<<<N_ROWS, THREADS>>>(A, B, labels);
    mse_reduce_kernel<<<1, 1024>>>(out);
}

// round 2
// speedup vs baseline: 1.1597x; 1.1597x over previous
#include <cuda_runtime.h>

#define N_ROWS 8192
#define D_DIM  1024
#define THREADS 256
#define NBLOCKS 256
#define WARPS_PER_BLOCK (THREADS / 32)
#define TOTAL_WARPS (NBLOCKS * WARPS_PER_BLOCK)          // 2048
#define ROWS_PER_WARP (N_ROWS / TOTAL_WARPS)             // 4
#define F4_PER_ROW (D_DIM / 4)                           // 256
#define F4_PER_LANE (F4_PER_ROW / 32)                    // 8

__device__ float        g_partial[NBLOCKS];
__device__ unsigned int g_count = 0;

__global__ __launch_bounds__(THREADS)
void fused_cosine_mse_kernel(const float* __restrict__ A,
                             const float* __restrict__ B,
                             const float* __restrict__ labels,
                             float* __restrict__ out) {
    const int t   = threadIdx.x;
    const int wid = t >> 5;
    const int lid = t & 31;
    const int gw  = blockIdx.x * WARPS_PER_BLOCK + wid;   // global warp id

    float acc = 0.0f;   // sum of squared errors over this warp's rows (same in all lanes)

    #pragma unroll
    for (int r = 0; r < ROWS_PER_WARP; r++) {
        const int row = gw * ROWS_PER_WARP + r;
        const float4* a4 = reinterpret_cast<const float4*>(A + (size_t)row * D_DIM);
        const float4* b4 = reinterpret_cast<const float4*>(B + (size_t)row * D_DIM);

        float4 av[F4_PER_LANE], bv[F4_PER_LANE];
        #pragma unroll
        for (int k = 0; k < F4_PER_LANE; k++) {
            av[k] = a4[lid + k * 32];
            bv[k] = b4[lid + k * 32];
        }

        float dot = 0.0f, na = 0.0f, nb = 0.0f;
        #pragma unroll
        for (int k = 0; k < F4_PER_LANE; k++) {
            dot += av[k].x * bv[k].x + av[k].y * bv[k].y + av[k].z * bv[k].z + av[k].w * bv[k].w;
            na  += av[k].x * av[k].x + av[k].y * av[k].y + av[k].z * av[k].z + av[k].w * av[k].w;
            nb  += bv[k].x * bv[k].x + bv[k].y * bv[k].y + bv[k].z * bv[k].z + bv[k].w * bv[k].w;
        }

        // Butterfly reduce: every lane ends with full-row sums
        #pragma unroll
        for (int off = 16; off > 0; off >>= 1) {
            dot += __shfl_xor_sync(0xFFFFFFFFu, dot, off);
            na  += __shfl_xor_sync(0xFFFFFFFFu, na,  off);
            nb  += __shfl_xor_sync(0xFFFFFFFFu, nb,  off);
        }

        const float score = dot * rsqrtf(na * nb);
        const float diff  = score - labels[row];   // same address per warp -> broadcast
        acc += diff * diff;
    }

    // Block reduction of 8 warp partials (lane 0 of each warp holds acc)
    __shared__ float s_warp[WARPS_PER_BLOCK];
    __shared__ bool  s_is_last;
    if (lid == 0) s_warp[wid] = acc;
    __syncthreads();

    if (t == 0) {
        float bsum = 0.0f;
        #pragma unroll
        for (int w = 0; w < WARPS_PER_BLOCK; w++) bsum += s_warp[w];
        g_partial[blockIdx.x] = bsum;
        __threadfence();
        const unsigned int prev = atomicAdd(&g_count, 1u);
        s_is_last = (prev == NBLOCKS - 1);
    }
    __syncthreads();

    if (s_is_last) {
        __threadfence();   // acquire: make all g_partial writes visible
        // 256 threads read 256 partials in fixed slots -> deterministic
        float v = g_partial[t];
        #pragma unroll
        for (int off = 16; off > 0; off >>= 1)
            v += __shfl_xor_sync(0xFFFFFFFFu, v, off);

        __shared__ float s_final[WARPS_PER_BLOCK];
        if (lid == 0) s_final[wid] = v;
        __syncthreads();

        if (t == 0) {
            float total = 0.0f;
            #pragma unroll
            for (int w = 0; w < WARPS_PER_BLOCK; w++) total += s_final[w];
            out[0] = total * (1.0f / (float)N_ROWS);
            g_count = 0;   // reset for next graph replay
        }
    }
}

extern "C" void kernel_launch(void* const* d_in, const int* in_sizes, int n_in,
                              void* d_out, int out_size) {
    const float* A      = (const float*)d_in[0];  // issues_1_geb [8192,1024]
    const float* B      = (const float*)d_in[1];  // issues_2_geb [8192,1024]
    const float* labels = (const float*)d_in[2];  // labels [8192]
    float* out = (float*)d_out;

    fused_cosine_mse_kernel<<<NBLOCKS, THREADS>>>(A, B, labels, out);
}

// round 3
// speedup vs baseline: 1.1800x; 1.0175x over previous
#include <cuda_runtime.h>

#define N_ROWS 8192
#define D_DIM  1024
#define THREADS 256
#define NBLOCKS 1024
#define WARPS_PER_BLOCK (THREADS / 32)                   // 8
#define TOTAL_WARPS (NBLOCKS * WARPS_PER_BLOCK)          // 8192 -> 1 row per warp
#define F4_PER_LANE (D_DIM / 4 / 32)                     // 8
#define PARTIALS_PER_THREAD (NBLOCKS / THREADS)          // 4

__device__ float        g_partial[NBLOCKS];
__device__ unsigned int g_count = 0;

__global__ __launch_bounds__(THREADS)
void fused_cosine_mse_kernel(const float* __restrict__ A,
                             const float* __restrict__ B,
                             const float* __restrict__ labels,
                             float* __restrict__ out) {
    const int t   = threadIdx.x;
    const int wid = t >> 5;
    const int lid = t & 31;
    const int row = blockIdx.x * WARPS_PER_BLOCK + wid;   // one row per warp

    const float4* a4 = reinterpret_cast<const float4*>(A + (size_t)row * D_DIM);
    const float4* b4 = reinterpret_cast<const float4*>(B + (size_t)row * D_DIM);

    float4 av[F4_PER_LANE], bv[F4_PER_LANE];
    #pragma unroll
    for (int k = 0; k < F4_PER_LANE; k++) {
        av[k] = a4[lid + k * 32];
        bv[k] = b4[lid + k * 32];
    }

    float dot = 0.0f, na = 0.0f, nb = 0.0f;
    #pragma unroll
    for (int k = 0; k < F4_PER_LANE; k++) {
        dot += av[k].x * bv[k].x + av[k].y * bv[k].y + av[k].z * bv[k].z + av[k].w * bv[k].w;
        na  += av[k].x * av[k].x + av[k].y * av[k].y + av[k].z * av[k].z + av[k].w * av[k].w;
        nb  += bv[k].x * bv[k].x + bv[k].y * bv[k].y + bv[k].z * bv[k].z + bv[k].w * bv[k].w;
    }

    // Butterfly reduce: every lane ends with full-row sums
    #pragma unroll
    for (int off = 16; off > 0; off >>= 1) {
        dot += __shfl_xor_sync(0xFFFFFFFFu, dot, off);
        na  += __shfl_xor_sync(0xFFFFFFFFu, na,  off);
        nb  += __shfl_xor_sync(0xFFFFFFFFu, nb,  off);
    }

    float acc = 0.0f;
    {
        const float score = dot * rsqrtf(na * nb);
        const float diff  = score - labels[row];   // broadcast read per warp
        acc = diff * diff;
    }

    // Block reduction of 8 warp values
    __shared__ float s_warp[WARPS_PER_BLOCK];
    __shared__ bool  s_is_last;
    if (lid == 0) s_warp[wid] = acc;
    __syncthreads();

    if (t == 0) {
        float bsum = 0.0f;
        #pragma unroll
        for (int w = 0; w < WARPS_PER_BLOCK; w++) bsum += s_warp[w];
        g_partial[blockIdx.x] = bsum;
        __threadfence();
        const unsigned int prev = atomicAdd(&g_count, 1u);
        s_is_last = (prev == NBLOCKS - 1);
    }
    __syncthreads();

    if (s_is_last) {
        __threadfence();   // acquire: all g_partial writes visible
        // Deterministic fixed-slot folding: thread t sums partials t, t+256, ...
        float v = 0.0f;
        #pragma unroll
        for (int i = 0; i < PARTIALS_PER_THREAD; i++)
            v += g_partial[t + i * THREADS];

        #pragma unroll
        for (int off = 16; off > 0; off >>= 1)
            v += __shfl_xor_sync(0xFFFFFFFFu, v, off);

        __shared__ float s_final[WARPS_PER_BLOCK];
        if (lid == 0) s_final[wid] = v;
        __syncthreads();

        if (t == 0) {
            float total = 0.0f;
            #pragma unroll
            for (int w = 0; w < WARPS_PER_BLOCK; w++) total += s_final[w];
            out[0] = total * (1.0f / (float)N_ROWS);
            g_count = 0;   // reset for next graph replay
        }
    }
}

extern "C" void kernel_launch(void* const* d_in, const int* in_sizes, int n_in,
                              void* d_out, int out_size) {
    const float* A      = (const float*)d_in[0];  // issues_1_geb [8192,1024]
    const float* B      = (const float*)d_in[1];  // issues_2_geb [8192,1024]
    const float* labels = (const float*)d_in[2];  // labels [8192]
    float* out = (float*)d_out;

    fused_cosine_mse_kernel<<<NBLOCKS, THREADS>>>(A, B, labels, out);
}

// round 4
// speedup vs baseline: 1.4048x; 1.1905x over previous
#include <cuda_runtime.h>

#define N_ROWS 8192
#define D_DIM  1024
#define THREADS 256
#define NBLOCKS 1024
#define WARPS_PER_BLOCK (THREADS / 32)                   // 8
#define F4_PER_LANE (D_DIM / 4 / 32)                     // 8
#define PARTIALS_PER_THREAD (NBLOCKS / THREADS)          // 4

__device__ float        g_partial[NBLOCKS];
__device__ unsigned int g_count = 0;

__global__ __launch_bounds__(THREADS, 7)   // cap regs ~36 -> 7 CTAs/SM -> grid fits in ONE wave
void fused_cosine_mse_kernel(const float* __restrict__ A,
                             const float* __restrict__ B,
                             const float* __restrict__ labels,
                             float* __restrict__ out) {
    const int t   = threadIdx.x;
    const int wid = t >> 5;
    const int lid = t & 31;
    const int row = blockIdx.x * WARPS_PER_BLOCK + wid;   // one row per warp

    const float4* a4 = reinterpret_cast<const float4*>(A + (size_t)row * D_DIM) + lid;
    const float4* b4 = reinterpret_cast<const float4*>(B + (size_t)row * D_DIM) + lid;

    // Front-batch the loads (streaming: no reuse, evict-first)
    float4 av[F4_PER_LANE], bv[F4_PER_LANE];
    #pragma unroll
    for (int k = 0; k < F4_PER_LANE; k++) {
        av[k] = __ldcs(a4 + k * 32);
        bv[k] = __ldcs(b4 + k * 32);
    }
    // Scheduling fence: keep compute from being hoisted between the loads
    asm volatile("" ::: "memory");

    float dot = 0.0f, na = 0.0f, nb = 0.0f;
    #pragma unroll
    for (int k = 0; k < F4_PER_LANE; k++) {
        dot += av[k].x * bv[k].x + av[k].y * bv[k].y + av[k].z * bv[k].z + av[k].w * bv[k].w;
        na  += av[k].x * av[k].x + av[k].y * av[k].y + av[k].z * av[k].z + av[k].w * av[k].w;
        nb  += bv[k].x * bv[k].x + bv[k].y * bv[k].y + bv[k].z * bv[k].z + bv[k].w * bv[k].w;
    }

    // Butterfly reduce: every lane ends with full-row sums
    #pragma unroll
    for (int off = 16; off > 0; off >>= 1) {
        dot += __shfl_xor_sync(0xFFFFFFFFu, dot, off);
        na  += __shfl_xor_sync(0xFFFFFFFFu, na,  off);
        nb  += __shfl_xor_sync(0xFFFFFFFFu, nb,  off);
    }

    const float score = dot * rsqrtf(na * nb);
    const float diff  = score - labels[row];   // broadcast read per warp
    const float acc   = diff * diff;

    // Block reduction of 8 warp values
    __shared__ float s_warp[WARPS_PER_BLOCK];
    __shared__ bool  s_is_last;
    if (lid == 0) s_warp[wid] = acc;
    __syncthreads();

    if (t == 0) {
        float bsum = 0.0f;
        #pragma unroll
        for (int w = 0; w < WARPS_PER_BLOCK; w++) bsum += s_warp[w];
        g_partial[blockIdx.x] = bsum;
        __threadfence();
        const unsigned int prev = atomicAdd(&g_count, 1u);
        s_is_last = (prev == NBLOCKS - 1);
    }
    __syncthreads();

    if (s_is_last) {
        __threadfence();   // acquire: all g_partial writes visible
        // Deterministic fixed-slot folding: thread t sums partials t, t+256, ...
        float v = 0.0f;
        #pragma unroll
        for (int i = 0; i < PARTIALS_PER_THREAD; i++)
            v += g_partial[t + i * THREADS];

        #pragma unroll
        for (int off = 16; off > 0; off >>= 1)
            v += __shfl_xor_sync(0xFFFFFFFFu, v, off);

        __shared__ float s_final[WARPS_PER_BLOCK];
        if (lid == 0) s_final[wid] = v;
        __syncthreads();

        if (t == 0) {
            float total = 0.0f;
            #pragma unroll
            for (int w = 0; w < WARPS_PER_BLOCK; w++) total += s_final[w];
            out[0] = total * (1.0f / (float)N_ROWS);
            g_count = 0;   // reset for next graph replay
        }
    }
}

extern "C" void kernel_launch(void* const* d_in, const int* in_sizes, int n_in,
                              void* d_out, int out_size) {
    const float* A      = (const float*)d_in[0];  // issues_1_geb [8192,1024]
    const float* B      = (const float*)d_in[1];  // issues_2_geb [8192,1024]
    const float* labels = (const float*)d_in[2];  // labels [8192]
    float* out = (float*)d_out;

    fused_cosine_mse_kernel<<<NBLOCKS, THREADS>>>(A, B, labels, out);
}